// round 13
// baseline (speedup 1.0000x reference)
#include <cuda_runtime.h>
#include <cuda_fp16.h>

// Problem constants (fixed by the dataset)
#define NMAX 100001
#define EMAX 1600000
#define IN_D 128
#define OUT_D 32
#define NHEAD 4

// Scratch (allocation-free: __device__ globals)
__device__ float g_Wh[(size_t)NMAX * OUT_D];
__device__ float g_asrc[(size_t)NMAX * NHEAD];
__device__ float g_adst[(size_t)NMAX * NHEAD];
__device__ float g_denom[(size_t)NMAX * NHEAD];     // later overwritten with 1/(denom+eps)
__device__ int   g_count[NMAX];
__device__ int   g_row[NMAX];
__device__ int   g_cursor[NMAX];
__device__ int   g_bsum[256];
__device__ float4 g_csr[EMAX];                      // 25.6 MB: {src, ex01(h2), ex23(h2), pad}

__device__ __forceinline__ void red_add_v4(float* p, float4 v) {
    asm volatile("red.global.add.v4.f32 [%0], {%1,%2,%3,%4};"
                 :: "l"(p), "f"(v.x), "f"(v.y), "f"(v.z), "f"(v.w) : "memory");
}

// ---------------------------------------------------------------------------
// Kernel 0: zero denom + count
// ---------------------------------------------------------------------------
__global__ void __launch_bounds__(256) k_zero(int N) {
    int i = blockIdx.x * 256 + threadIdx.x;
    if (i < N) {
        *reinterpret_cast<float4*>(&g_denom[(size_t)i * 4]) = make_float4(0.f, 0.f, 0.f, 0.f);
        g_count[i] = 0;
    }
}

// ---------------------------------------------------------------------------
// Kernel 1: Wh = feat @ W^T + b ; a_src/a_dst projections
// 256 threads, 256 nodes/block, 8 nodes x 4 dims per thread (td=t&7, tn=t>>3).
// W staged in smem (amortized over 8 nodes: 4 W-LDS per 128 FMAs); features
// read via broadcast __ldg (lanes sharing tn read the same float4).
// Smem: sW 16384 + sA 1024 = 17408 B. 391 blocks -> single wave.
// ---------------------------------------------------------------------------
__global__ void __launch_bounds__(256) k_proj(
    const float* __restrict__ feat, const float* __restrict__ W,
    const float* __restrict__ bias, const float* __restrict__ attS,
    const float* __restrict__ attD, int N)
{
    __shared__ float sW[IN_D * OUT_D];      // transposed: sW[k*32+d]
    __shared__ float sA[2 * NHEAD * OUT_D];

    int tid = threadIdx.x;
    int node0 = blockIdx.x * 256;

    #pragma unroll
    for (int i = 0; i < 16; i++) {
        int idx = tid + i * 256;            // idx = d*128 + k
        int d = idx >> 7, k = idx & 127;
        sW[k * 32 + d] = W[idx];
    }
    sA[tid] = (tid < 128) ? attS[tid] : attD[tid - 128];
    __syncthreads();

    int td = tid & 7, tn = tid >> 3;        // tn in [0,32): nodes 8tn .. 8tn+7
    int gn[8];
    #pragma unroll
    for (int j = 0; j < 8; j++) {
        int g = node0 + tn * 8 + j;
        gn[j] = (g < N) ? g : (N - 1);      // clamp for safe loads; stores guarded
    }

    float acc[8][4];
    #pragma unroll
    for (int c = 0; c < 4; c++) {
        float bb = __ldg(&bias[td * 4 + c]);
        #pragma unroll
        for (int j = 0; j < 8; j++) acc[j][c] = bb;
    }

    const float4* f4 = reinterpret_cast<const float4*>(feat);
    #pragma unroll 2
    for (int k4 = 0; k4 < 32; k4++) {
        float4 w0 = *reinterpret_cast<float4*>(&sW[(k4 * 4 + 0) * 32 + td * 4]);
        float4 w1 = *reinterpret_cast<float4*>(&sW[(k4 * 4 + 1) * 32 + td * 4]);
        float4 w2 = *reinterpret_cast<float4*>(&sW[(k4 * 4 + 2) * 32 + td * 4]);
        float4 w3 = *reinterpret_cast<float4*>(&sW[(k4 * 4 + 3) * 32 + td * 4]);
        #pragma unroll
        for (int j = 0; j < 8; j++) {
            float4 f = __ldg(&f4[(size_t)gn[j] * 32 + k4]);   // broadcast across td lanes
            acc[j][0] += f.x * w0.x + f.y * w1.x + f.z * w2.x + f.w * w3.x;
            acc[j][1] += f.x * w0.y + f.y * w1.y + f.z * w2.y + f.w * w3.y;
            acc[j][2] += f.x * w0.z + f.y * w1.z + f.z * w2.z + f.w * w3.z;
            acc[j][3] += f.x * w0.w + f.y * w1.w + f.z * w2.w + f.w * w3.w;
        }
    }

    #pragma unroll
    for (int j = 0; j < 8; j++) {
        int g = node0 + tn * 8 + j;
        if (g < N) {
            *reinterpret_cast<float4*>(&g_Wh[(size_t)g * 32 + td * 4]) =
                make_float4(acc[j][0], acc[j][1], acc[j][2], acc[j][3]);
        }
        #pragma unroll
        for (int h = 0; h < NHEAD; h++) {
            const float* as = &sA[h * 32 + td * 4];
            const float* ad = &sA[128 + h * 32 + td * 4];
            float ps = acc[j][0] * as[0] + acc[j][1] * as[1] + acc[j][2] * as[2] + acc[j][3] * as[3];
            float pd = acc[j][0] * ad[0] + acc[j][1] * ad[1] + acc[j][2] * ad[2] + acc[j][3] * ad[3];
            ps += __shfl_down_sync(0xffffffffu, ps, 4);
            ps += __shfl_down_sync(0xffffffffu, ps, 2);
            ps += __shfl_down_sync(0xffffffffu, ps, 1);
            pd += __shfl_down_sync(0xffffffffu, pd, 4);
            pd += __shfl_down_sync(0xffffffffu, pd, 2);
            pd += __shfl_down_sync(0xffffffffu, pd, 1);
            if (td == 0 && g < N) {
                g_asrc[(size_t)g * 4 + h] = ps;
                g_adst[(size_t)g * 4 + h] = pd;
            }
        }
    }
}

// ---------------------------------------------------------------------------
// Kernel 2: histogram of dst only
// ---------------------------------------------------------------------------
__global__ void __launch_bounds__(256) k_hist(const int* __restrict__ dst, int E) {
    int e = blockIdx.x * 256 + threadIdx.x;
    if (e < E) atomicAdd(&g_count[__ldg(&dst[e])], 1);
}

// ---------------------------------------------------------------------------
// Scan: exclusive prefix sum of count -> row (3 small kernels)
// ---------------------------------------------------------------------------
__global__ void __launch_bounds__(1024) k_scan_a(int N) {
    __shared__ int warp_sums[32];
    int b = blockIdx.x, t = threadIdx.x;
    int idx = b * 1024 + t;
    int v = (idx < N) ? g_count[idx] : 0;
    int lane = t & 31, w = t >> 5;
    int x = v;
    #pragma unroll
    for (int o = 1; o < 32; o <<= 1) {
        int y = __shfl_up_sync(0xffffffffu, x, o);
        if (lane >= o) x += y;
    }
    if (lane == 31) warp_sums[w] = x;
    __syncthreads();
    if (w == 0) {
        int s = warp_sums[lane];
        #pragma unroll
        for (int o = 1; o < 32; o <<= 1) {
            int y = __shfl_up_sync(0xffffffffu, s, o);
            if (lane >= o) s += y;
        }
        warp_sums[lane] = s;
    }
    __syncthreads();
    int warp_off = (w > 0) ? warp_sums[w - 1] : 0;
    if (idx < N) g_row[idx] = warp_off + x - v;   // exclusive
    if (t == 0) g_bsum[b] = warp_sums[31];        // block total
}

__global__ void __launch_bounds__(256) k_scan_b(int NB) {
    __shared__ int s[256];
    int t = threadIdx.x;
    s[t] = (t < NB) ? g_bsum[t] : 0;
    __syncthreads();
    #pragma unroll
    for (int o = 1; o < 256; o <<= 1) {
        int v = (t >= o) ? s[t - o] : 0;
        __syncthreads();
        s[t] += v;
        __syncthreads();
    }
    if (t < NB) g_bsum[t] = s[t];                 // inclusive
}

__global__ void __launch_bounds__(1024) k_scan_c(int N) {
    int idx = blockIdx.x * 1024 + threadIdx.x;
    if (idx >= N) return;
    int b = idx >> 10;
    int off = (b > 0) ? g_bsum[b - 1] : 0;
    int r = g_row[idx] + off;
    g_row[idx] = r;
    g_cursor[idx] = r;
}

// ---------------------------------------------------------------------------
// Kernel 3 (fused): per-edge exp, denom[src] reduction, 16B-record scatter.
// Global max cancels in softmax (denominator eps perturbation ~1e-16) -> skip.
// Record: {src:int, ex01:half2, ex23:half2, pad} as one float4.
// ---------------------------------------------------------------------------
__global__ void __launch_bounds__(256) k_edge_fused(const int* __restrict__ ei, int E) {
    int e = blockIdx.x * 256 + threadIdx.x;
    if (e >= E) return;
    int s = __ldg(&ei[e]);
    int d = __ldg(&ei[E + e]);
    float4 as = *reinterpret_cast<const float4*>(&g_asrc[(size_t)s * 4]);
    float4 ad = *reinterpret_cast<const float4*>(&g_adst[(size_t)d * 4]);
    float4 ex; float v;
    v = as.x + ad.x; v = v > 0.f ? v : 0.2f * v; ex.x = __expf(v);
    v = as.y + ad.y; v = v > 0.f ? v : 0.2f * v; ex.y = __expf(v);
    v = as.z + ad.z; v = v > 0.f ? v : 0.2f * v; ex.z = __expf(v);
    v = as.w + ad.w; v = v > 0.f ? v : 0.2f * v; ex.w = __expf(v);
    red_add_v4(&g_denom[(size_t)s * 4], ex);
    int pos = atomicAdd(&g_cursor[d], 1);
    __half2 h01 = __floats2half2_rn(ex.x, ex.y);
    __half2 h23 = __floats2half2_rn(ex.z, ex.w);
    float4 r;
    r.x = __int_as_float(s);
    r.y = __uint_as_float(*reinterpret_cast<unsigned*>(&h01));
    r.z = __uint_as_float(*reinterpret_cast<unsigned*>(&h23));
    r.w = 0.f;
    g_csr[pos] = r;                                // single STG.128
}

// ---------------------------------------------------------------------------
// Kernel 4: denom -> 1/(denom + eps) in place
// ---------------------------------------------------------------------------
__global__ void __launch_bounds__(256) k_rcp(int N) {
    int i = blockIdx.x * 256 + threadIdx.x;
    if (i >= N) return;
    float4 d = *reinterpret_cast<float4*>(&g_denom[(size_t)i * 4]);
    d.x = 1.f / (d.x + 1e-16f);
    d.y = 1.f / (d.y + 1e-16f);
    d.z = 1.f / (d.z + 1e-16f);
    d.w = 1.f / (d.w + 1e-16f);
    *reinterpret_cast<float4*>(&g_denom[(size_t)i * 4]) = d;
}

// ---------------------------------------------------------------------------
// Kernel 5: gather — warp per dst node, register accumulation, one store.
// lane l: h = l>>3, q = l&7 owns out[node][h*32 + 4q .. 4q+3].
// ---------------------------------------------------------------------------
__device__ __forceinline__ float rec_ex(float4 r, int h) {
    unsigned u01 = __float_as_uint(r.y);
    unsigned u23 = __float_as_uint(r.z);
    __half2 h01 = *reinterpret_cast<__half2*>(&u01);
    __half2 h23 = *reinterpret_cast<__half2*>(&u23);
    float2 f01 = __half22float2(h01);
    float2 f23 = __half22float2(h23);
    float e = f01.x;
    e = (h == 1) ? f01.y : e;
    e = (h == 2) ? f23.x : e;
    e = (h == 3) ? f23.y : e;
    return e;
}

__global__ void __launch_bounds__(256) k_gather(float* __restrict__ out, int N) {
    int warp = threadIdx.x >> 5;
    int lane = threadIdx.x & 31;
    int node = blockIdx.x * 8 + warp;
    if (node >= N) return;
    int start = __ldg(&g_row[node]);
    int cnt   = __ldg(&g_count[node]);
    int h = lane >> 3, q = lane & 7;

    float4 acc = make_float4(0.f, 0.f, 0.f, 0.f);
    int i = 0;
    for (; i + 8 <= cnt; i += 8) {
        int p = start + i;
        float4 r[8];
        #pragma unroll
        for (int u = 0; u < 8; u++) r[u] = __ldg(&g_csr[p + u]);
        int sidx[8];
        #pragma unroll
        for (int u = 0; u < 8; u++) sidx[u] = __float_as_int(r[u].x);
        float4 w[8];
        #pragma unroll
        for (int u = 0; u < 8; u++)
            w[u] = __ldg(reinterpret_cast<const float4*>(&g_Wh[(size_t)sidx[u] * 32 + q * 4]));
        float a[8];
        #pragma unroll
        for (int u = 0; u < 8; u++)
            a[u] = rec_ex(r[u], h) * __ldg(&g_denom[(size_t)sidx[u] * 4 + h]);
        #pragma unroll
        for (int u = 0; u < 8; u++) {
            acc.x += a[u] * w[u].x;
            acc.y += a[u] * w[u].y;
            acc.z += a[u] * w[u].z;
            acc.w += a[u] * w[u].w;
        }
    }
    for (; i < cnt; i++) {
        int p = start + i;
        float4 r0 = __ldg(&g_csr[p]);
        int s0 = __float_as_int(r0.x);
        float a0 = rec_ex(r0, h) * __ldg(&g_denom[(size_t)s0 * 4 + h]);
        float4 w0 = __ldg(reinterpret_cast<const float4*>(&g_Wh[(size_t)s0 * 32 + q * 4]));
        acc.x += a0 * w0.x; acc.y += a0 * w0.y; acc.z += a0 * w0.z; acc.w += a0 * w0.w;
    }
    *reinterpret_cast<float4*>(&out[(size_t)node * 128 + lane * 4]) = acc;
}

// ---------------------------------------------------------------------------
extern "C" void kernel_launch(void* const* d_in, const int* in_sizes, int n_in,
                              void* d_out, int out_size) {
    const float* feat = (const float*)d_in[0];
    const float* W    = (const float*)d_in[1];
    const float* b    = (const float*)d_in[2];
    const float* attS = (const float*)d_in[3];
    const float* attD = (const float*)d_in[4];
    const int*   ei   = (const int*)d_in[5];
    float* out = (float*)d_out;

    int N = in_sizes[0] / IN_D;
    int E = in_sizes[5] / 2;

    int NB = (N + 1023) / 1024;     // <= 256 for N <= 262144

    k_zero<<<(N + 255) / 256, 256>>>(N);
    k_hist<<<(E + 255) / 256, 256>>>(ei + E, E);
    k_scan_a<<<NB, 1024>>>(N);
    k_proj<<<(N + 255) / 256, 256>>>(feat, W, b, attS, attD, N);  // slot #4 for ncu
    k_scan_b<<<1, 256>>>(NB);
    k_scan_c<<<NB, 1024>>>(N);
    k_edge_fused<<<(E + 255) / 256, 256>>>(ei, E);
    k_rcp<<<(N + 255) / 256, 256>>>(N);
    k_gather<<<(N + 7) / 8, 256>>>(out, N);
}

// round 14
// speedup vs baseline: 1.0374x; 1.0374x over previous
#include <cuda_runtime.h>
#include <cuda_fp16.h>

// Problem constants (fixed by the dataset)
#define NMAX 100001
#define EMAX 1600000
#define IN_D 128
#define OUT_D 32
#define NHEAD 4

// Scratch (allocation-free: __device__ globals)
__device__ float g_Wh[(size_t)NMAX * OUT_D];
__device__ float g_asrc[(size_t)NMAX * NHEAD];
__device__ float g_adst[(size_t)NMAX * NHEAD];
__device__ float g_denom[(size_t)NMAX * NHEAD];     // later overwritten with 1/(denom+eps)
__device__ int   g_count[NMAX];
__device__ int   g_row[NMAX];
__device__ int   g_cursor[NMAX];
__device__ int   g_bsum[256];
__device__ float4 g_csr[EMAX];                      // 25.6 MB: {src, ex01(h2), ex23(h2), pad}

__device__ __forceinline__ void red_add_v4(float* p, float4 v) {
    asm volatile("red.global.add.v4.f32 [%0], {%1,%2,%3,%4};"
                 :: "l"(p), "f"(v.x), "f"(v.y), "f"(v.z), "f"(v.w) : "memory");
}

// ---------------------------------------------------------------------------
// Kernel 0: zero denom + count
// ---------------------------------------------------------------------------
__global__ void __launch_bounds__(256) k_zero(int N) {
    int i = blockIdx.x * 256 + threadIdx.x;
    if (i < N) {
        *reinterpret_cast<float4*>(&g_denom[(size_t)i * 4]) = make_float4(0.f, 0.f, 0.f, 0.f);
        g_count[i] = 0;
    }
}

// ---------------------------------------------------------------------------
// Kernel 1 (R9 config — empirical optimum): Wh = feat @ W^T + b ; a_src/a_dst.
// 256 threads, 128 nodes/block, 4 nodes x 4 dims per thread.
// Dynamic smem: sW 16384 + sF 67584 (128x132 padded) + sA 1024 = 84992 B.
// ---------------------------------------------------------------------------
#define PROJ_SMEM (16384 + 128 * 132 * 4 + 1024)

__global__ void __launch_bounds__(256) k_proj(
    const float* __restrict__ feat, const float* __restrict__ W,
    const float* __restrict__ bias, const float* __restrict__ attS,
    const float* __restrict__ attD, int N)
{
    extern __shared__ float smem[];
    float* sW = smem;                  // [128 k][32 d] transposed
    float* sF = smem + 4096;           // 128 rows x 132 floats (padded)
    float* sA = smem + 4096 + 128 * 132;

    int tid = threadIdx.x;
    int node0 = blockIdx.x * 128;

    #pragma unroll
    for (int i = 0; i < 16; i++) {
        int idx = tid + i * 256;            // idx = d*128 + k
        int d = idx >> 7, k = idx & 127;
        sW[k * 32 + d] = W[idx];
    }
    sA[tid] = (tid < 128) ? attS[tid] : attD[tid - 128];

    const float4* f4 = reinterpret_cast<const float4*>(feat);
    #pragma unroll
    for (int i = 0; i < 16; i++) {
        int idx = tid + i * 256;            // 0..4095
        int n = idx >> 5, c = idx & 31;
        int gn = node0 + n;
        float4 v = (gn < N) ? f4[(size_t)gn * 32 + c] : make_float4(0.f, 0.f, 0.f, 0.f);
        *reinterpret_cast<float4*>(&sF[n * 132 + c * 4]) = v;
    }
    __syncthreads();

    int td = tid & 7, tn = tid >> 3;        // tn in [0,32): nodes 4tn .. 4tn+3
    float acc[4][4];
    #pragma unroll
    for (int c = 0; c < 4; c++) {
        float bb = __ldg(&bias[td * 4 + c]);
        acc[0][c] = bb; acc[1][c] = bb; acc[2][c] = bb; acc[3][c] = bb;
    }

    #pragma unroll 2
    for (int k4 = 0; k4 < 32; k4++) {
        float4 w0 = *reinterpret_cast<float4*>(&sW[(k4 * 4 + 0) * 32 + td * 4]);
        float4 w1 = *reinterpret_cast<float4*>(&sW[(k4 * 4 + 1) * 32 + td * 4]);
        float4 w2 = *reinterpret_cast<float4*>(&sW[(k4 * 4 + 2) * 32 + td * 4]);
        float4 w3 = *reinterpret_cast<float4*>(&sW[(k4 * 4 + 3) * 32 + td * 4]);
        #pragma unroll
        for (int j = 0; j < 4; j++) {
            float4 f = *reinterpret_cast<float4*>(&sF[(tn * 4 + j) * 132 + k4 * 4]);
            acc[j][0] += f.x * w0.x + f.y * w1.x + f.z * w2.x + f.w * w3.x;
            acc[j][1] += f.x * w0.y + f.y * w1.y + f.z * w2.y + f.w * w3.y;
            acc[j][2] += f.x * w0.z + f.y * w1.z + f.z * w2.z + f.w * w3.z;
            acc[j][3] += f.x * w0.w + f.y * w1.w + f.z * w2.w + f.w * w3.w;
        }
    }

    #pragma unroll
    for (int j = 0; j < 4; j++) {
        int gn = node0 + tn * 4 + j;
        if (gn < N) {
            *reinterpret_cast<float4*>(&g_Wh[(size_t)gn * 32 + td * 4]) =
                make_float4(acc[j][0], acc[j][1], acc[j][2], acc[j][3]);
        }
        #pragma unroll
        for (int h = 0; h < NHEAD; h++) {
            const float* as = &sA[h * 32 + td * 4];
            const float* ad = &sA[128 + h * 32 + td * 4];
            float ps = acc[j][0] * as[0] + acc[j][1] * as[1] + acc[j][2] * as[2] + acc[j][3] * as[3];
            float pd = acc[j][0] * ad[0] + acc[j][1] * ad[1] + acc[j][2] * ad[2] + acc[j][3] * ad[3];
            ps += __shfl_down_sync(0xffffffffu, ps, 4);
            ps += __shfl_down_sync(0xffffffffu, ps, 2);
            ps += __shfl_down_sync(0xffffffffu, ps, 1);
            pd += __shfl_down_sync(0xffffffffu, pd, 4);
            pd += __shfl_down_sync(0xffffffffu, pd, 2);
            pd += __shfl_down_sync(0xffffffffu, pd, 1);
            if (td == 0 && gn < N) {
                g_asrc[(size_t)gn * 4 + h] = ps;
                g_adst[(size_t)gn * 4 + h] = pd;
            }
        }
    }
}

// ---------------------------------------------------------------------------
// Kernel 2: histogram of dst only
// ---------------------------------------------------------------------------
__global__ void __launch_bounds__(256) k_hist(const int* __restrict__ dst, int E) {
    int e = blockIdx.x * 256 + threadIdx.x;
    if (e < E) atomicAdd(&g_count[__ldg(&dst[e])], 1);
}

// ---------------------------------------------------------------------------
// Scan: block-local exclusive scan (k_scan_a) then fixup that also sums the
// preceding block totals in-kernel (k_scan_c) — scan_b eliminated.
// ---------------------------------------------------------------------------
__global__ void __launch_bounds__(1024) k_scan_a(int N) {
    __shared__ int warp_sums[32];
    int b = blockIdx.x, t = threadIdx.x;
    int idx = b * 1024 + t;
    int v = (idx < N) ? g_count[idx] : 0;
    int lane = t & 31, w = t >> 5;
    int x = v;
    #pragma unroll
    for (int o = 1; o < 32; o <<= 1) {
        int y = __shfl_up_sync(0xffffffffu, x, o);
        if (lane >= o) x += y;
    }
    if (lane == 31) warp_sums[w] = x;
    __syncthreads();
    if (w == 0) {
        int s = warp_sums[lane];
        #pragma unroll
        for (int o = 1; o < 32; o <<= 1) {
            int y = __shfl_up_sync(0xffffffffu, s, o);
            if (lane >= o) s += y;
        }
        warp_sums[lane] = s;
    }
    __syncthreads();
    int warp_off = (w > 0) ? warp_sums[w - 1] : 0;
    if (idx < N) g_row[idx] = warp_off + x - v;   // exclusive (block-local)
    if (t == 0) g_bsum[b] = warp_sums[31];        // block total (unscanned)
}

__global__ void __launch_bounds__(1024) k_scan_c(int N) {
    __shared__ int s_off;
    int b = blockIdx.x, t = threadIdx.x;
    if (t < 32) {
        int partial = 0;
        for (int i = t; i < b; i += 32) partial += g_bsum[i];
        #pragma unroll
        for (int o = 16; o > 0; o >>= 1)
            partial += __shfl_down_sync(0xffffffffu, partial, o);
        if (t == 0) s_off = partial;
    }
    __syncthreads();
    int idx = b * 1024 + t;
    if (idx < N) {
        int r = g_row[idx] + s_off;
        g_row[idx] = r;
        g_cursor[idx] = r;
    }
}

// ---------------------------------------------------------------------------
// Kernel 3 (fused): per-edge exp, denom[src] reduction, 16B-record scatter.
// Global max cancels in softmax (denominator eps perturbation ~1e-16) -> skip.
// Record: {src:int, ex01:half2, ex23:half2, pad} as one float4.
// ---------------------------------------------------------------------------
__global__ void __launch_bounds__(256) k_edge_fused(const int* __restrict__ ei, int E) {
    int e = blockIdx.x * 256 + threadIdx.x;
    if (e >= E) return;
    int s = __ldg(&ei[e]);
    int d = __ldg(&ei[E + e]);
    float4 as = *reinterpret_cast<const float4*>(&g_asrc[(size_t)s * 4]);
    float4 ad = *reinterpret_cast<const float4*>(&g_adst[(size_t)d * 4]);
    float4 ex; float v;
    v = as.x + ad.x; v = v > 0.f ? v : 0.2f * v; ex.x = __expf(v);
    v = as.y + ad.y; v = v > 0.f ? v : 0.2f * v; ex.y = __expf(v);
    v = as.z + ad.z; v = v > 0.f ? v : 0.2f * v; ex.z = __expf(v);
    v = as.w + ad.w; v = v > 0.f ? v : 0.2f * v; ex.w = __expf(v);
    red_add_v4(&g_denom[(size_t)s * 4], ex);
    int pos = atomicAdd(&g_cursor[d], 1);
    __half2 h01 = __floats2half2_rn(ex.x, ex.y);
    __half2 h23 = __floats2half2_rn(ex.z, ex.w);
    float4 r;
    r.x = __int_as_float(s);
    r.y = __uint_as_float(*reinterpret_cast<unsigned*>(&h01));
    r.z = __uint_as_float(*reinterpret_cast<unsigned*>(&h23));
    r.w = 0.f;
    g_csr[pos] = r;                                // single STG.128
}

// ---------------------------------------------------------------------------
// Kernel 4: denom -> 1/(denom + eps) in place
// ---------------------------------------------------------------------------
__global__ void __launch_bounds__(256) k_rcp(int N) {
    int i = blockIdx.x * 256 + threadIdx.x;
    if (i >= N) return;
    float4 d = *reinterpret_cast<float4*>(&g_denom[(size_t)i * 4]);
    d.x = 1.f / (d.x + 1e-16f);
    d.y = 1.f / (d.y + 1e-16f);
    d.z = 1.f / (d.z + 1e-16f);
    d.w = 1.f / (d.w + 1e-16f);
    *reinterpret_cast<float4*>(&g_denom[(size_t)i * 4]) = d;
}

// ---------------------------------------------------------------------------
// Kernel 5: gather — warp per dst node, register accumulation, one store.
// lane l: h = l>>3, q = l&7 owns out[node][h*32 + 4q .. 4q+3].
// Single predicated 8-wide loop: tail iterations keep full MLP (clamped
// indices, zeroed alpha) instead of a latency-serial remainder loop.
// ---------------------------------------------------------------------------
__device__ __forceinline__ float rec_ex(float4 r, int h) {
    unsigned u01 = __float_as_uint(r.y);
    unsigned u23 = __float_as_uint(r.z);
    __half2 h01 = *reinterpret_cast<__half2*>(&u01);
    __half2 h23 = *reinterpret_cast<__half2*>(&u23);
    float2 f01 = __half22float2(h01);
    float2 f23 = __half22float2(h23);
    float e = f01.x;
    e = (h == 1) ? f01.y : e;
    e = (h == 2) ? f23.x : e;
    e = (h == 3) ? f23.y : e;
    return e;
}

__global__ void __launch_bounds__(256) k_gather(float* __restrict__ out, int N, int E) {
    int warp = threadIdx.x >> 5;
    int lane = threadIdx.x & 31;
    int node = blockIdx.x * 8 + warp;
    if (node >= N) return;
    int start = __ldg(&g_row[node]);
    int cnt   = __ldg(&g_count[node]);
    int h = lane >> 3, q = lane & 7;

    float4 acc = make_float4(0.f, 0.f, 0.f, 0.f);
    for (int i = 0; i < cnt; i += 8) {
        float4 r[8]; int sidx[8]; bool ok[8];
        #pragma unroll
        for (int u = 0; u < 8; u++) {
            ok[u] = (i + u) < cnt;
            int p = start + i + u;
            p = (p < E) ? p : (E - 1);          // clamp: loads safe, alpha zeroed
            r[u] = __ldg(&g_csr[p]);
        }
        #pragma unroll
        for (int u = 0; u < 8; u++) sidx[u] = __float_as_int(r[u].x);
        float4 w[8];
        #pragma unroll
        for (int u = 0; u < 8; u++)
            w[u] = __ldg(reinterpret_cast<const float4*>(&g_Wh[(size_t)sidx[u] * 32 + q * 4]));
        float a[8];
        #pragma unroll
        for (int u = 0; u < 8; u++) {
            float av = rec_ex(r[u], h) * __ldg(&g_denom[(size_t)sidx[u] * 4 + h]);
            a[u] = ok[u] ? av : 0.f;
        }
        #pragma unroll
        for (int u = 0; u < 8; u++) {
            acc.x += a[u] * w[u].x;
            acc.y += a[u] * w[u].y;
            acc.z += a[u] * w[u].z;
            acc.w += a[u] * w[u].w;
        }
    }
    *reinterpret_cast<float4*>(&out[(size_t)node * 128 + lane * 4]) = acc;
}

// ---------------------------------------------------------------------------
extern "C" void kernel_launch(void* const* d_in, const int* in_sizes, int n_in,
                              void* d_out, int out_size) {
    const float* feat = (const float*)d_in[0];
    const float* W    = (const float*)d_in[1];
    const float* b    = (const float*)d_in[2];
    const float* attS = (const float*)d_in[3];
    const float* attD = (const float*)d_in[4];
    const int*   ei   = (const int*)d_in[5];
    float* out = (float*)d_out;

    int N = in_sizes[0] / IN_D;
    int E = in_sizes[5] / 2;

    int NB = (N + 1023) / 1024;     // <= 256 for N <= 262144

    // Opt-in to >48KB dynamic smem for k_proj (idempotent; not a stream op)
    cudaFuncSetAttribute(k_proj, cudaFuncAttributeMaxDynamicSharedMemorySize, PROJ_SMEM);

    k_zero<<<(N + 255) / 256, 256>>>(N);
    k_hist<<<(E + 255) / 256, 256>>>(ei + E, E);
    k_scan_a<<<NB, 1024>>>(N);
    k_proj<<<(N + 127) / 128, 256, PROJ_SMEM>>>(feat, W, b, attS, attD, N);  // slot #4 for ncu
    k_scan_c<<<NB, 1024>>>(N);
    k_edge_fused<<<(E + 255) / 256, 256>>>(ei, E);
    k_rcp<<<(N + 255) / 256, 256>>>(N);
    k_gather<<<(N + 7) / 8, 256>>>(out, N, E);
}

// round 16
// speedup vs baseline: 1.2356x; 1.1910x over previous
#include <cuda_runtime.h>
#include <cuda_fp16.h>

// Problem constants (fixed by the dataset)
#define NMAX 100001
#define EMAX 1600000
#define IN_D 128
#define OUT_D 32
#define NHEAD 4

// Scratch (allocation-free: __device__ globals)
__device__ __half2 g_Wh16[(size_t)NMAX * 16];       // Wh in fp16: 16 half2 per row (64B)
__device__ float g_asrc[(size_t)NMAX * NHEAD];
__device__ float g_adst[(size_t)NMAX * NHEAD];
__device__ float g_denom[(size_t)NMAX * NHEAD];     // later overwritten with 1/(denom+eps)
__device__ int   g_count[NMAX];
__device__ int   g_row[NMAX];
__device__ int   g_cursor[NMAX];
__device__ int   g_bsum[256];
__device__ float4 g_csr[EMAX];                      // 25.6 MB: {src, ex01(h2), ex23(h2), pad}

__device__ __forceinline__ void red_add_v4(float* p, float4 v) {
    asm volatile("red.global.add.v4.f32 [%0], {%1,%2,%3,%4};"
                 :: "l"(p), "f"(v.x), "f"(v.y), "f"(v.z), "f"(v.w) : "memory");
}

// ---------------------------------------------------------------------------
// Kernel 0: zero denom + count
// ---------------------------------------------------------------------------
__global__ void __launch_bounds__(256) k_zero(int N) {
    int i = blockIdx.x * 256 + threadIdx.x;
    if (i < N) {
        *reinterpret_cast<float4*>(&g_denom[(size_t)i * 4]) = make_float4(0.f, 0.f, 0.f, 0.f);
        g_count[i] = 0;
    }
}

// ---------------------------------------------------------------------------
// Kernel 1 (R9 config — empirical optimum): Wh = feat @ W^T + b ; a_src/a_dst.
// 256 threads, 128 nodes/block, 4 nodes x 4 dims per thread.
// Dynamic smem: sW 16384 + sF 67584 (128x132 padded) + sA 1024 = 84992 B.
// Wh stored as half2 (only consumer is k_gather).
// ---------------------------------------------------------------------------
#define PROJ_SMEM (16384 + 128 * 132 * 4 + 1024)

__global__ void __launch_bounds__(256) k_proj(
    const float* __restrict__ feat, const float* __restrict__ W,
    const float* __restrict__ bias, const float* __restrict__ attS,
    const float* __restrict__ attD, int N)
{
    extern __shared__ float smem[];
    float* sW = smem;                  // [128 k][32 d] transposed
    float* sF = smem + 4096;           // 128 rows x 132 floats (padded)
    float* sA = smem + 4096 + 128 * 132;

    int tid = threadIdx.x;
    int node0 = blockIdx.x * 128;

    #pragma unroll
    for (int i = 0; i < 16; i++) {
        int idx = tid + i * 256;            // idx = d*128 + k
        int d = idx >> 7, k = idx & 127;
        sW[k * 32 + d] = W[idx];
    }
    sA[tid] = (tid < 128) ? attS[tid] : attD[tid - 128];

    const float4* f4 = reinterpret_cast<const float4*>(feat);
    #pragma unroll
    for (int i = 0; i < 16; i++) {
        int idx = tid + i * 256;            // 0..4095
        int n = idx >> 5, c = idx & 31;
        int gn = node0 + n;
        float4 v = (gn < N) ? f4[(size_t)gn * 32 + c] : make_float4(0.f, 0.f, 0.f, 0.f);
        *reinterpret_cast<float4*>(&sF[n * 132 + c * 4]) = v;
    }
    __syncthreads();

    int td = tid & 7, tn = tid >> 3;        // tn in [0,32): nodes 4tn .. 4tn+3
    float acc[4][4];
    #pragma unroll
    for (int c = 0; c < 4; c++) {
        float bb = __ldg(&bias[td * 4 + c]);
        acc[0][c] = bb; acc[1][c] = bb; acc[2][c] = bb; acc[3][c] = bb;
    }

    #pragma unroll 2
    for (int k4 = 0; k4 < 32; k4++) {
        float4 w0 = *reinterpret_cast<float4*>(&sW[(k4 * 4 + 0) * 32 + td * 4]);
        float4 w1 = *reinterpret_cast<float4*>(&sW[(k4 * 4 + 1) * 32 + td * 4]);
        float4 w2 = *reinterpret_cast<float4*>(&sW[(k4 * 4 + 2) * 32 + td * 4]);
        float4 w3 = *reinterpret_cast<float4*>(&sW[(k4 * 4 + 3) * 32 + td * 4]);
        #pragma unroll
        for (int j = 0; j < 4; j++) {
            float4 f = *reinterpret_cast<float4*>(&sF[(tn * 4 + j) * 132 + k4 * 4]);
            acc[j][0] += f.x * w0.x + f.y * w1.x + f.z * w2.x + f.w * w3.x;
            acc[j][1] += f.x * w0.y + f.y * w1.y + f.z * w2.y + f.w * w3.y;
            acc[j][2] += f.x * w0.z + f.y * w1.z + f.z * w2.z + f.w * w3.z;
            acc[j][3] += f.x * w0.w + f.y * w1.w + f.z * w2.w + f.w * w3.w;
        }
    }

    #pragma unroll
    for (int j = 0; j < 4; j++) {
        int gn = node0 + tn * 4 + j;
        if (gn < N) {
            __half2 h0 = __floats2half2_rn(acc[j][0], acc[j][1]);
            __half2 h1 = __floats2half2_rn(acc[j][2], acc[j][3]);
            uint2 pk;
            pk.x = *reinterpret_cast<unsigned*>(&h0);
            pk.y = *reinterpret_cast<unsigned*>(&h1);
            *reinterpret_cast<uint2*>(&g_Wh16[(size_t)gn * 16 + td * 2]) = pk;
        }
        #pragma unroll
        for (int h = 0; h < NHEAD; h++) {
            const float* as = &sA[h * 32 + td * 4];
            const float* ad = &sA[128 + h * 32 + td * 4];
            float ps = acc[j][0] * as[0] + acc[j][1] * as[1] + acc[j][2] * as[2] + acc[j][3] * as[3];
            float pd = acc[j][0] * ad[0] + acc[j][1] * ad[1] + acc[j][2] * ad[2] + acc[j][3] * ad[3];
            ps += __shfl_down_sync(0xffffffffu, ps, 4);
            ps += __shfl_down_sync(0xffffffffu, ps, 2);
            ps += __shfl_down_sync(0xffffffffu, ps, 1);
            pd += __shfl_down_sync(0xffffffffu, pd, 4);
            pd += __shfl_down_sync(0xffffffffu, pd, 2);
            pd += __shfl_down_sync(0xffffffffu, pd, 1);
            if (td == 0 && gn < N) {
                g_asrc[(size_t)gn * 4 + h] = ps;
                g_adst[(size_t)gn * 4 + h] = pd;
            }
        }
    }
}

// ---------------------------------------------------------------------------
// Kernel 2: histogram of dst only
// ---------------------------------------------------------------------------
__global__ void __launch_bounds__(256) k_hist(const int* __restrict__ dst, int E) {
    int e = blockIdx.x * 256 + threadIdx.x;
    if (e < E) atomicAdd(&g_count[__ldg(&dst[e])], 1);
}

// ---------------------------------------------------------------------------
// Scan: exclusive prefix sum of count -> row (3 small kernels, R9 version)
// ---------------------------------------------------------------------------
__global__ void __launch_bounds__(1024) k_scan_a(int N) {
    __shared__ int warp_sums[32];
    int b = blockIdx.x, t = threadIdx.x;
    int idx = b * 1024 + t;
    int v = (idx < N) ? g_count[idx] : 0;
    int lane = t & 31, w = t >> 5;
    int x = v;
    #pragma unroll
    for (int o = 1; o < 32; o <<= 1) {
        int y = __shfl_up_sync(0xffffffffu, x, o);
        if (lane >= o) x += y;
    }
    if (lane == 31) warp_sums[w] = x;
    __syncthreads();
    if (w == 0) {
        int s = warp_sums[lane];
        #pragma unroll
        for (int o = 1; o < 32; o <<= 1) {
            int y = __shfl_up_sync(0xffffffffu, s, o);
            if (lane >= o) s += y;
        }
        warp_sums[lane] = s;
    }
    __syncthreads();
    int warp_off = (w > 0) ? warp_sums[w - 1] : 0;
    if (idx < N) g_row[idx] = warp_off + x - v;   // exclusive
    if (t == 0) g_bsum[b] = warp_sums[31];        // block total
}

__global__ void __launch_bounds__(256) k_scan_b(int NB) {
    __shared__ int s[256];
    int t = threadIdx.x;
    s[t] = (t < NB) ? g_bsum[t] : 0;
    __syncthreads();
    #pragma unroll
    for (int o = 1; o < 256; o <<= 1) {
        int v = (t >= o) ? s[t - o] : 0;
        __syncthreads();
        s[t] += v;
        __syncthreads();
    }
    if (t < NB) g_bsum[t] = s[t];                 // inclusive
}

__global__ void __launch_bounds__(1024) k_scan_c(int N) {
    int idx = blockIdx.x * 1024 + threadIdx.x;
    if (idx >= N) return;
    int b = idx >> 10;
    int off = (b > 0) ? g_bsum[b - 1] : 0;
    int r = g_row[idx] + off;
    g_row[idx] = r;
    g_cursor[idx] = r;
}

// ---------------------------------------------------------------------------
// Kernel 3 (fused): per-edge exp, denom[src] reduction, 16B-record scatter.
// Global max cancels in softmax (denominator eps perturbation ~1e-16) -> skip.
// Record: {src:int, ex01:half2, ex23:half2, pad} as one float4.
// ---------------------------------------------------------------------------
__global__ void __launch_bounds__(256) k_edge_fused(const int* __restrict__ ei, int E) {
    int e = blockIdx.x * 256 + threadIdx.x;
    if (e >= E) return;
    int s = __ldg(&ei[e]);
    int d = __ldg(&ei[E + e]);
    float4 as = *reinterpret_cast<const float4*>(&g_asrc[(size_t)s * 4]);
    float4 ad = *reinterpret_cast<const float4*>(&g_adst[(size_t)d * 4]);
    float4 ex; float v;
    v = as.x + ad.x; v = v > 0.f ? v : 0.2f * v; ex.x = __expf(v);
    v = as.y + ad.y; v = v > 0.f ? v : 0.2f * v; ex.y = __expf(v);
    v = as.z + ad.z; v = v > 0.f ? v : 0.2f * v; ex.z = __expf(v);
    v = as.w + ad.w; v = v > 0.f ? v : 0.2f * v; ex.w = __expf(v);
    red_add_v4(&g_denom[(size_t)s * 4], ex);
    int pos = atomicAdd(&g_cursor[d], 1);
    __half2 h01 = __floats2half2_rn(ex.x, ex.y);
    __half2 h23 = __floats2half2_rn(ex.z, ex.w);
    float4 r;
    r.x = __int_as_float(s);
    r.y = __uint_as_float(*reinterpret_cast<unsigned*>(&h01));
    r.z = __uint_as_float(*reinterpret_cast<unsigned*>(&h23));
    r.w = 0.f;
    g_csr[pos] = r;                                // single STG.128
}

// ---------------------------------------------------------------------------
// Kernel 4: denom -> 1/(denom + eps) in place
// ---------------------------------------------------------------------------
__global__ void __launch_bounds__(256) k_rcp(int N) {
    int i = blockIdx.x * 256 + threadIdx.x;
    if (i >= N) return;
    float4 d = *reinterpret_cast<float4*>(&g_denom[(size_t)i * 4]);
    d.x = 1.f / (d.x + 1e-16f);
    d.y = 1.f / (d.y + 1e-16f);
    d.z = 1.f / (d.z + 1e-16f);
    d.w = 1.f / (d.w + 1e-16f);
    *reinterpret_cast<float4*>(&g_denom[(size_t)i * 4]) = d;
}

// ---------------------------------------------------------------------------
// Kernel 5: gather — warp per dst node (R9 structure: 8-wide main + scalar
// tail), Wh read as half2 (8B per record per q-lane instead of 16B).
// lane l: h = l>>3, q = l&7 owns out[node][h*32 + 4q .. 4q+3].
// ---------------------------------------------------------------------------
__device__ __forceinline__ float rec_ex(float4 r, int h) {
    unsigned u01 = __float_as_uint(r.y);
    unsigned u23 = __float_as_uint(r.z);
    __half2 h01 = *reinterpret_cast<__half2*>(&u01);
    __half2 h23 = *reinterpret_cast<__half2*>(&u23);
    float2 f01 = __half22float2(h01);
    float2 f23 = __half22float2(h23);
    float e = f01.x;
    e = (h == 1) ? f01.y : e;
    e = (h == 2) ? f23.x : e;
    e = (h == 3) ? f23.y : e;
    return e;
}

__device__ __forceinline__ void wh_pair(uint2 pk, float2& f0, float2& f1) {
    __half2 p0 = *reinterpret_cast<__half2*>(&pk.x);
    __half2 p1 = *reinterpret_cast<__half2*>(&pk.y);
    f0 = __half22float2(p0);
    f1 = __half22float2(p1);
}

__global__ void __launch_bounds__(256) k_gather(float* __restrict__ out, int N) {
    int warp = threadIdx.x >> 5;
    int lane = threadIdx.x & 31;
    int node = blockIdx.x * 8 + warp;
    if (node >= N) return;
    int start = __ldg(&g_row[node]);
    int cnt   = __ldg(&g_count[node]);
    int h = lane >> 3, q = lane & 7;

    float4 acc = make_float4(0.f, 0.f, 0.f, 0.f);
    int i = 0;
    for (; i + 8 <= cnt; i += 8) {
        int p = start + i;
        float4 r[8];
        #pragma unroll
        for (int u = 0; u < 8; u++) r[u] = __ldg(&g_csr[p + u]);
        int sidx[8];
        #pragma unroll
        for (int u = 0; u < 8; u++) sidx[u] = __float_as_int(r[u].x);
        uint2 wv[8];
        #pragma unroll
        for (int u = 0; u < 8; u++)
            wv[u] = __ldg(reinterpret_cast<const uint2*>(&g_Wh16[(size_t)sidx[u] * 16 + q * 2]));
        float a[8];
        #pragma unroll
        for (int u = 0; u < 8; u++)
            a[u] = rec_ex(r[u], h) * __ldg(&g_denom[(size_t)sidx[u] * 4 + h]);
        #pragma unroll
        for (int u = 0; u < 8; u++) {
            float2 f0, f1;
            wh_pair(wv[u], f0, f1);
            acc.x += a[u] * f0.x;
            acc.y += a[u] * f0.y;
            acc.z += a[u] * f1.x;
            acc.w += a[u] * f1.y;
        }
    }
    for (; i < cnt; i++) {
        int p = start + i;
        float4 r0 = __ldg(&g_csr[p]);
        int s0 = __float_as_int(r0.x);
        float a0 = rec_ex(r0, h) * __ldg(&g_denom[(size_t)s0 * 4 + h]);
        uint2 wv0 = __ldg(reinterpret_cast<const uint2*>(&g_Wh16[(size_t)s0 * 16 + q * 2]));
        float2 f0, f1;
        wh_pair(wv0, f0, f1);
        acc.x += a0 * f0.x; acc.y += a0 * f0.y; acc.z += a0 * f1.x; acc.w += a0 * f1.y;
    }
    *reinterpret_cast<float4*>(&out[(size_t)node * 128 + lane * 4]) = acc;
}

// ---------------------------------------------------------------------------
extern "C" void kernel_launch(void* const* d_in, const int* in_sizes, int n_in,
                              void* d_out, int out_size) {
    const float* feat = (const float*)d_in[0];
    const float* W    = (const float*)d_in[1];
    const float* b    = (const float*)d_in[2];
    const float* attS = (const float*)d_in[3];
    const float* attD = (const float*)d_in[4];
    const int*   ei   = (const int*)d_in[5];
    float* out = (float*)d_out;

    int N = in_sizes[0] / IN_D;
    int E = in_sizes[5] / 2;

    int NB = (N + 1023) / 1024;     // <= 256 for N <= 262144

    // Opt-in to >48KB dynamic smem for k_proj (idempotent; not a stream op)
    cudaFuncSetAttribute(k_proj, cudaFuncAttributeMaxDynamicSharedMemorySize, PROJ_SMEM);

    k_zero<<<(N + 255) / 256, 256>>>(N);
    k_hist<<<(E + 255) / 256, 256>>>(ei + E, E);
    k_scan_a<<<NB, 1024>>>(N);
    k_proj<<<(N + 127) / 128, 256, PROJ_SMEM>>>(feat, W, b, attS, attD, N);  // slot #4 for ncu
    k_scan_b<<<1, 256>>>(NB);
    k_scan_c<<<NB, 1024>>>(N);
    k_edge_fused<<<(E + 255) / 256, 256>>>(ei, E);
    k_rcp<<<(N + 255) / 256, 256>>>(N);
    k_gather<<<(N + 7) / 8, 256>>>(out, N);
}

// round 17
// speedup vs baseline: 1.2748x; 1.0317x over previous
#include <cuda_runtime.h>
#include <cuda_fp16.h>

// Problem constants (fixed by the dataset)
#define NMAX 100001
#define EMAX 1600000
#define IN_D 128
#define OUT_D 32
#define NHEAD 4

// Scratch (allocation-free: __device__ globals)
__device__ __half2 g_Wh16[(size_t)NMAX * 16];       // Wh in fp16: 16 half2 per row (64B)
__device__ float g_asrc[(size_t)NMAX * NHEAD];
__device__ float g_adst[(size_t)NMAX * NHEAD];
__device__ float g_denom[(size_t)NMAX * NHEAD];     // later overwritten with 1/(denom+eps)
__device__ int   g_count[NMAX];
__device__ int   g_row[NMAX];
__device__ int   g_cursor[NMAX];
__device__ int   g_bsum[256];
__device__ float4 g_csr[EMAX];                      // 25.6 MB: {src, ex01(h2), ex23(h2), pad}

__device__ __forceinline__ void red_add_v4(float* p, float4 v) {
    asm volatile("red.global.add.v4.f32 [%0], {%1,%2,%3,%4};"
                 :: "l"(p), "f"(v.x), "f"(v.y), "f"(v.z), "f"(v.w) : "memory");
}

// ---------------------------------------------------------------------------
// Kernel 0: zero denom + count
// ---------------------------------------------------------------------------
__global__ void __launch_bounds__(256) k_zero(int N) {
    int i = blockIdx.x * 256 + threadIdx.x;
    if (i < N) {
        *reinterpret_cast<float4*>(&g_denom[(size_t)i * 4]) = make_float4(0.f, 0.f, 0.f, 0.f);
        g_count[i] = 0;
    }
}

// ---------------------------------------------------------------------------
// Kernel 1: Wh = feat @ W^T + b ; a_src/a_dst projections.
// 256 threads, 128 nodes/block, 4 nodes x 4 dims per thread — R9 tile shape,
// but features staged in TWO K=64 chunks so smem fits 4 CTAs/SM:
//   sW 16384 + sF 128x68x4=34816 + sA 1024 = 52224 B  (occ 23% -> 50%).
// Wh stored as half2 (only consumer is k_gather).
// ---------------------------------------------------------------------------
#define SF_STRIDE 68
#define PROJ_SMEM (16384 + 128 * SF_STRIDE * 4 + 1024)

__global__ void __launch_bounds__(256) k_proj(
    const float* __restrict__ feat, const float* __restrict__ W,
    const float* __restrict__ bias, const float* __restrict__ attS,
    const float* __restrict__ attD, int N)
{
    extern __shared__ float smem[];
    float* sW = smem;                       // [128 k][32 d] transposed
    float* sF = smem + 4096;                // 128 rows x 68 floats (one K=64 chunk)
    float* sA = smem + 4096 + 128 * SF_STRIDE;

    int tid = threadIdx.x;
    int node0 = blockIdx.x * 128;

    #pragma unroll
    for (int i = 0; i < 16; i++) {
        int idx = tid + i * 256;            // idx = d*128 + k
        int d = idx >> 7, k = idx & 127;
        sW[k * 32 + d] = W[idx];
    }
    sA[tid] = (tid < 128) ? attS[tid] : attD[tid - 128];

    int td = tid & 7, tn = tid >> 3;        // tn in [0,32): nodes 4tn .. 4tn+3
    float acc[4][4];
    #pragma unroll
    for (int c = 0; c < 4; c++) {
        float bb = __ldg(&bias[td * 4 + c]);
        acc[0][c] = bb; acc[1][c] = bb; acc[2][c] = bb; acc[3][c] = bb;
    }

    const float4* f4 = reinterpret_cast<const float4*>(feat);

    #pragma unroll
    for (int kk = 0; kk < 2; kk++) {        // K chunks: [0,64), [64,128)
        __syncthreads();                    // protect sF reuse across chunks
        // Load 128 nodes x 16 float4 (64 floats) for this chunk
        #pragma unroll
        for (int i = 0; i < 8; i++) {
            int idx = tid + i * 256;        // 0..2047
            int n = idx >> 4, c = idx & 15; // node, float4-col within chunk
            int gn = node0 + n;
            float4 v = (gn < N) ? f4[(size_t)gn * 32 + kk * 16 + c]
                                : make_float4(0.f, 0.f, 0.f, 0.f);
            *reinterpret_cast<float4*>(&sF[n * SF_STRIDE + c * 4]) = v;
        }
        __syncthreads();

        #pragma unroll 2
        for (int k4c = 0; k4c < 16; k4c++) {
            int k4 = kk * 16 + k4c;
            float4 w0 = *reinterpret_cast<float4*>(&sW[(k4 * 4 + 0) * 32 + td * 4]);
            float4 w1 = *reinterpret_cast<float4*>(&sW[(k4 * 4 + 1) * 32 + td * 4]);
            float4 w2 = *reinterpret_cast<float4*>(&sW[(k4 * 4 + 2) * 32 + td * 4]);
            float4 w3 = *reinterpret_cast<float4*>(&sW[(k4 * 4 + 3) * 32 + td * 4]);
            #pragma unroll
            for (int j = 0; j < 4; j++) {
                float4 f = *reinterpret_cast<float4*>(&sF[(tn * 4 + j) * SF_STRIDE + k4c * 4]);
                acc[j][0] += f.x * w0.x + f.y * w1.x + f.z * w2.x + f.w * w3.x;
                acc[j][1] += f.x * w0.y + f.y * w1.y + f.z * w2.y + f.w * w3.y;
                acc[j][2] += f.x * w0.z + f.y * w1.z + f.z * w2.z + f.w * w3.z;
                acc[j][3] += f.x * w0.w + f.y * w1.w + f.z * w2.w + f.w * w3.w;
            }
        }
    }

    #pragma unroll
    for (int j = 0; j < 4; j++) {
        int gn = node0 + tn * 4 + j;
        if (gn < N) {
            __half2 h0 = __floats2half2_rn(acc[j][0], acc[j][1]);
            __half2 h1 = __floats2half2_rn(acc[j][2], acc[j][3]);
            uint2 pk;
            pk.x = *reinterpret_cast<unsigned*>(&h0);
            pk.y = *reinterpret_cast<unsigned*>(&h1);
            *reinterpret_cast<uint2*>(&g_Wh16[(size_t)gn * 16 + td * 2]) = pk;
        }
        #pragma unroll
        for (int h = 0; h < NHEAD; h++) {
            const float* as = &sA[h * 32 + td * 4];
            const float* ad = &sA[128 + h * 32 + td * 4];
            float ps = acc[j][0] * as[0] + acc[j][1] * as[1] + acc[j][2] * as[2] + acc[j][3] * as[3];
            float pd = acc[j][0] * ad[0] + acc[j][1] * ad[1] + acc[j][2] * ad[2] + acc[j][3] * ad[3];
            ps += __shfl_down_sync(0xffffffffu, ps, 4);
            ps += __shfl_down_sync(0xffffffffu, ps, 2);
            ps += __shfl_down_sync(0xffffffffu, ps, 1);
            pd += __shfl_down_sync(0xffffffffu, pd, 4);
            pd += __shfl_down_sync(0xffffffffu, pd, 2);
            pd += __shfl_down_sync(0xffffffffu, pd, 1);
            if (td == 0 && gn < N) {
                g_asrc[(size_t)gn * 4 + h] = ps;
                g_adst[(size_t)gn * 4 + h] = pd;
            }
        }
    }
}

// ---------------------------------------------------------------------------
// Kernel 2: histogram of dst only
// ---------------------------------------------------------------------------
__global__ void __launch_bounds__(256) k_hist(const int* __restrict__ dst, int E) {
    int e = blockIdx.x * 256 + threadIdx.x;
    if (e < E) atomicAdd(&g_count[__ldg(&dst[e])], 1);
}

// ---------------------------------------------------------------------------
// Scan: exclusive prefix sum of count -> row (3 small kernels)
// ---------------------------------------------------------------------------
__global__ void __launch_bounds__(1024) k_scan_a(int N) {
    __shared__ int warp_sums[32];
    int b = blockIdx.x, t = threadIdx.x;
    int idx = b * 1024 + t;
    int v = (idx < N) ? g_count[idx] : 0;
    int lane = t & 31, w = t >> 5;
    int x = v;
    #pragma unroll
    for (int o = 1; o < 32; o <<= 1) {
        int y = __shfl_up_sync(0xffffffffu, x, o);
        if (lane >= o) x += y;
    }
    if (lane == 31) warp_sums[w] = x;
    __syncthreads();
    if (w == 0) {
        int s = warp_sums[lane];
        #pragma unroll
        for (int o = 1; o < 32; o <<= 1) {
            int y = __shfl_up_sync(0xffffffffu, s, o);
            if (lane >= o) s += y;
        }
        warp_sums[lane] = s;
    }
    __syncthreads();
    int warp_off = (w > 0) ? warp_sums[w - 1] : 0;
    if (idx < N) g_row[idx] = warp_off + x - v;   // exclusive
    if (t == 0) g_bsum[b] = warp_sums[31];        // block total
}

__global__ void __launch_bounds__(256) k_scan_b(int NB) {
    __shared__ int s[256];
    int t = threadIdx.x;
    s[t] = (t < NB) ? g_bsum[t] : 0;
    __syncthreads();
    #pragma unroll
    for (int o = 1; o < 256; o <<= 1) {
        int v = (t >= o) ? s[t - o] : 0;
        __syncthreads();
        s[t] += v;
        __syncthreads();
    }
    if (t < NB) g_bsum[t] = s[t];                 // inclusive
}

__global__ void __launch_bounds__(1024) k_scan_c(int N) {
    int idx = blockIdx.x * 1024 + threadIdx.x;
    if (idx >= N) return;
    int b = idx >> 10;
    int off = (b > 0) ? g_bsum[b - 1] : 0;
    int r = g_row[idx] + off;
    g_row[idx] = r;
    g_cursor[idx] = r;
}

// ---------------------------------------------------------------------------
// Kernel 3 (fused): per-edge exp, denom[src] reduction, 16B-record scatter.
// Global max cancels in softmax (denominator eps perturbation ~1e-16) -> skip.
// Record: {src:int, ex01:half2, ex23:half2, pad} as one float4.
// ---------------------------------------------------------------------------
__global__ void __launch_bounds__(256) k_edge_fused(const int* __restrict__ ei, int E) {
    int e = blockIdx.x * 256 + threadIdx.x;
    if (e >= E) return;
    int s = __ldg(&ei[e]);
    int d = __ldg(&ei[E + e]);
    float4 as = *reinterpret_cast<const float4*>(&g_asrc[(size_t)s * 4]);
    float4 ad = *reinterpret_cast<const float4*>(&g_adst[(size_t)d * 4]);
    float4 ex; float v;
    v = as.x + ad.x; v = v > 0.f ? v : 0.2f * v; ex.x = __expf(v);
    v = as.y + ad.y; v = v > 0.f ? v : 0.2f * v; ex.y = __expf(v);
    v = as.z + ad.z; v = v > 0.f ? v : 0.2f * v; ex.z = __expf(v);
    v = as.w + ad.w; v = v > 0.f ? v : 0.2f * v; ex.w = __expf(v);
    red_add_v4(&g_denom[(size_t)s * 4], ex);
    int pos = atomicAdd(&g_cursor[d], 1);
    __half2 h01 = __floats2half2_rn(ex.x, ex.y);
    __half2 h23 = __floats2half2_rn(ex.z, ex.w);
    float4 r;
    r.x = __int_as_float(s);
    r.y = __uint_as_float(*reinterpret_cast<unsigned*>(&h01));
    r.z = __uint_as_float(*reinterpret_cast<unsigned*>(&h23));
    r.w = 0.f;
    g_csr[pos] = r;                                // single STG.128
}

// ---------------------------------------------------------------------------
// Kernel 4: denom -> 1/(denom + eps) in place
// ---------------------------------------------------------------------------
__global__ void __launch_bounds__(256) k_rcp(int N) {
    int i = blockIdx.x * 256 + threadIdx.x;
    if (i >= N) return;
    float4 d = *reinterpret_cast<float4*>(&g_denom[(size_t)i * 4]);
    d.x = 1.f / (d.x + 1e-16f);
    d.y = 1.f / (d.y + 1e-16f);
    d.z = 1.f / (d.z + 1e-16f);
    d.w = 1.f / (d.w + 1e-16f);
    *reinterpret_cast<float4*>(&g_denom[(size_t)i * 4]) = d;
}

// ---------------------------------------------------------------------------
// Kernel 5: gather — warp per dst node (8-wide main + scalar tail), Wh as half2.
// lane l: h = l>>3, q = l&7 owns out[node][h*32 + 4q .. 4q+3].
// ---------------------------------------------------------------------------
__device__ __forceinline__ float rec_ex(float4 r, int h) {
    unsigned u01 = __float_as_uint(r.y);
    unsigned u23 = __float_as_uint(r.z);
    __half2 h01 = *reinterpret_cast<__half2*>(&u01);
    __half2 h23 = *reinterpret_cast<__half2*>(&u23);
    float2 f01 = __half22float2(h01);
    float2 f23 = __half22float2(h23);
    float e = f01.x;
    e = (h == 1) ? f01.y : e;
    e = (h == 2) ? f23.x : e;
    e = (h == 3) ? f23.y : e;
    return e;
}

__device__ __forceinline__ void wh_pair(uint2 pk, float2& f0, float2& f1) {
    __half2 p0 = *reinterpret_cast<__half2*>(&pk.x);
    __half2 p1 = *reinterpret_cast<__half2*>(&pk.y);
    f0 = __half22float2(p0);
    f1 = __half22float2(p1);
}

__global__ void __launch_bounds__(256) k_gather(float* __restrict__ out, int N) {
    int warp = threadIdx.x >> 5;
    int lane = threadIdx.x & 31;
    int node = blockIdx.x * 8 + warp;
    if (node >= N) return;
    int start = __ldg(&g_row[node]);
    int cnt   = __ldg(&g_count[node]);
    int h = lane >> 3, q = lane & 7;

    float4 acc = make_float4(0.f, 0.f, 0.f, 0.f);
    int i = 0;
    for (; i + 8 <= cnt; i += 8) {
        int p = start + i;
        float4 r[8];
        #pragma unroll
        for (int u = 0; u < 8; u++) r[u] = __ldg(&g_csr[p + u]);
        int sidx[8];
        #pragma unroll
        for (int u = 0; u < 8; u++) sidx[u] = __float_as_int(r[u].x);
        uint2 wv[8];
        #pragma unroll
        for (int u = 0; u < 8; u++)
            wv[u] = __ldg(reinterpret_cast<const uint2*>(&g_Wh16[(size_t)sidx[u] * 16 + q * 2]));
        float a[8];
        #pragma unroll
        for (int u = 0; u < 8; u++)
            a[u] = rec_ex(r[u], h) * __ldg(&g_denom[(size_t)sidx[u] * 4 + h]);
        #pragma unroll
        for (int u = 0; u < 8; u++) {
            float2 f0, f1;
            wh_pair(wv[u], f0, f1);
            acc.x += a[u] * f0.x;
            acc.y += a[u] * f0.y;
            acc.z += a[u] * f1.x;
            acc.w += a[u] * f1.y;
        }
    }
    for (; i < cnt; i++) {
        int p = start + i;
        float4 r0 = __ldg(&g_csr[p]);
        int s0 = __float_as_int(r0.x);
        float a0 = rec_ex(r0, h) * __ldg(&g_denom[(size_t)s0 * 4 + h]);
        uint2 wv0 = __ldg(reinterpret_cast<const uint2*>(&g_Wh16[(size_t)s0 * 16 + q * 2]));
        float2 f0, f1;
        wh_pair(wv0, f0, f1);
        acc.x += a0 * f0.x; acc.y += a0 * f0.y; acc.z += a0 * f1.x; acc.w += a0 * f1.y;
    }
    *reinterpret_cast<float4*>(&out[(size_t)node * 128 + lane * 4]) = acc;
}

// ---------------------------------------------------------------------------
extern "C" void kernel_launch(void* const* d_in, const int* in_sizes, int n_in,
                              void* d_out, int out_size) {
    const float* feat = (const float*)d_in[0];
    const float* W    = (const float*)d_in[1];
    const float* b    = (const float*)d_in[2];
    const float* attS = (const float*)d_in[3];
    const float* attD = (const float*)d_in[4];
    const int*   ei   = (const int*)d_in[5];
    float* out = (float*)d_out;

    int N = in_sizes[0] / IN_D;
    int E = in_sizes[5] / 2;

    int NB = (N + 1023) / 1024;     // <= 256 for N <= 262144

    // Opt-in to >48KB dynamic smem for k_proj (idempotent; not a stream op)
    cudaFuncSetAttribute(k_proj, cudaFuncAttributeMaxDynamicSharedMemorySize, PROJ_SMEM);

    k_zero<<<(N + 255) / 256, 256>>>(N);
    k_hist<<<(E + 255) / 256, 256>>>(ei + E, E);
    k_scan_a<<<NB, 1024>>>(N);
    k_proj<<<(N + 127) / 128, 256, PROJ_SMEM>>>(feat, W, b, attS, attD, N);  // slot #4 for ncu
    k_scan_b<<<1, 256>>>(NB);
    k_scan_c<<<NB, 1024>>>(N);
    k_edge_fused<<<(E + 255) / 256, 256>>>(ei, E);
    k_rcp<<<(N + 255) / 256, 256>>>(N);
    k_gather<<<(N + 7) / 8, 256>>>(out, N);
}